// round 1
// baseline (speedup 1.0000x reference)
#include <cuda_runtime.h>
#include <cuda_bf16.h>
#include <math_constants.h>

// Problem constants (fixed by dataset): N=65536, D_LAT=64, K=64, D_DATA=512.
#define KC     64     // number of clusters
#define DL     64     // latent dim
#define RPB    128    // rows per block in main kernel
#define PAD    68     // padded row stride (floats) for xs/rs tiles: 68%4==0 (float4 ok),
                      // bank = (4*i + d) % 32 -> only 4-way conflict on scalar col access
#define ALPHA_C 0.001f
#define EPS_C   1e-8f

// Persistent device state (no cudaMalloc allowed)
__device__ float g_C[KC * DL];      // centroids
__device__ float g_c2[KC];          // ||C_j||^2
__device__ float g_S[KC * DL];      // accumulator r^T @ enc
__device__ float g_rsum[KC];        // column sums of r
__device__ float g_loss;            // sum_i sum_j r*d2 (final iter only)
__device__ float g_dec;             // sum (X - decoding)^2

// ---------------------------------------------------------------------------
// Init: C = enc[:K], c2 = rowsum(C^2), zero accumulators
// ---------------------------------------------------------------------------
__global__ void init_kernel(const float* __restrict__ enc) {
    int t = threadIdx.x;                  // 256 threads, 1 block
    for (int i = t; i < KC * DL; i += 256) {
        float v = enc[i];
        g_C[i] = v;
        g_S[i] = 0.0f;
    }
    if (t < KC) g_rsum[t] = 0.0f;
    if (t == 0) { g_loss = 0.0f; g_dec = 0.0f; }
    __syncthreads();
    if (t < KC) {
        float s = 0.0f;
        #pragma unroll 8
        for (int d = 0; d < DL; d++) { float c = g_C[t * DL + d]; s += c * c; }
        g_c2[t] = s;
    }
}

// ---------------------------------------------------------------------------
// Decoder loss: sum((X - dec)^2), float4 grid-stride
// ---------------------------------------------------------------------------
__global__ void decoder_kernel(const float4* __restrict__ X4,
                               const float4* __restrict__ D4, int n4) {
    __shared__ float red[32];
    float acc = 0.0f;
    int stride = gridDim.x * blockDim.x;
    for (int i = blockIdx.x * blockDim.x + threadIdx.x; i < n4; i += stride) {
        float4 x = X4[i], d = D4[i];
        float a = x.x - d.x, b = x.y - d.y, c = x.z - d.z, e = x.w - d.w;
        acc += a * a + b * b;
        acc += c * c + e * e;
    }
    // block reduce
    #pragma unroll
    for (int o = 16; o > 0; o >>= 1) acc += __shfl_down_sync(0xffffffffu, acc, o);
    int w = threadIdx.x >> 5;
    if ((threadIdx.x & 31) == 0) red[w] = acc;
    __syncthreads();
    if (threadIdx.x == 0) {
        float s = 0.0f;
        int nw = blockDim.x >> 5;
        for (int i = 0; i < nw; i++) s += red[i];
        atomicAdd(&g_dec, s);
    }
}

// ---------------------------------------------------------------------------
// Main fused iteration kernel:
//  phase 1: d2[i][j] = max(x2 + c2_j - 2 * x_i . C_j, 0)
//  phase 2: r = softmax(-d2) rowwise; loss_i = sum_j r*d2 (if doLoss)
//  phase 3: block-local S += r^T @ x, rsum += colsum(r)  (if doUpdate)
// ---------------------------------------------------------------------------
extern __shared__ float sm[];

__global__ __launch_bounds__(RPB)
void main_kernel(const float* __restrict__ enc, int N, int doLoss, int doUpdate) {
    float* Cs  = sm;                       // KC*DL = 4096
    float* c2s = Cs + KC * DL;             // 64
    float* xs  = c2s + KC;                 // RPB*PAD = 8704 (offset 4160, %4==0)
    float* rs  = xs + RPB * PAD;           // RPB*PAD (offset 12864, %4==0)
    __shared__ float red[32];

    const int tid  = threadIdx.x;
    const int row0 = blockIdx.x * RPB;

    // --- load C and c2 (coalesced) ---
    for (int i = tid; i < KC * DL; i += RPB) Cs[i] = g_C[i];
    if (tid < KC) c2s[tid] = g_c2[tid];

    // --- load x tile (coalesced float4), zero-fill OOB rows ---
    {
        const float4* enc4 = (const float4*)enc;
        const int NV = DL / 4;  // 16 float4 per row
        for (int idx = tid; idx < RPB * NV; idx += RPB) {
            int i = idx / NV, q = idx % NV;
            float4 v;
            if (row0 + i < N) v = enc4[(long)(row0 + i) * NV + q];
            else              v = make_float4(0.f, 0.f, 0.f, 0.f);
            *(float4*)(xs + i * PAD + 4 * q) = v;
        }
    }
    __syncthreads();

    const bool valid = (row0 + tid) < N;
    float lossv = 0.0f;

    if (valid) {
        // x row into registers
        float4 xv[DL / 4];
        #pragma unroll
        for (int k = 0; k < DL / 4; k++) xv[k] = *(const float4*)(xs + tid * PAD + 4 * k);
        float x2 = 0.0f;
        #pragma unroll
        for (int k = 0; k < DL / 4; k++)
            x2 += xv[k].x * xv[k].x + xv[k].y * xv[k].y + xv[k].z * xv[k].z + xv[k].w * xv[k].w;

        // phase 1: d2 per cluster -> rs row ; track min
        float mn = CUDART_INF_F;
        #pragma unroll 2
        for (int j = 0; j < KC; j++) {
            const float4* cp = (const float4*)(Cs + j * DL);
            float a0 = 0.f, a1 = 0.f, a2 = 0.f, a3 = 0.f;
            #pragma unroll
            for (int k = 0; k < DL / 4; k++) {
                float4 c = cp[k];
                a0 += xv[k].x * c.x; a1 += xv[k].y * c.y;
                a2 += xv[k].z * c.z; a3 += xv[k].w * c.w;
            }
            float g  = (a0 + a1) + (a2 + a3);
            float d2 = fmaxf(x2 + c2s[j] - 2.0f * g, 0.0f);
            mn = fminf(mn, d2);
            rs[tid * PAD + j] = d2;
        }

        // phase 2: softmax(-d2) rowwise (max-shifted: exp(mn - d2), mn = min d2)
        float Z = 0.0f, ed2 = 0.0f;
        #pragma unroll 4
        for (int j = 0; j < KC; j++) {
            float d2 = rs[tid * PAD + j];
            float e  = __expf(mn - d2);
            Z   += e;
            ed2 += e * d2;
            rs[tid * PAD + j] = e;
        }
        float inv = 1.0f / Z;  // Z >= 1 always (argmin term contributes exp(0)=1)
        #pragma unroll 4
        for (int j = 0; j < KC; j++) rs[tid * PAD + j] *= inv;
        lossv = ed2 * inv;
    } else {
        #pragma unroll 4
        for (int j = 0; j < KC; j++) rs[tid * PAD + j] = 0.0f;
    }

    if (doLoss) {
        float v = lossv;
        #pragma unroll
        for (int o = 16; o > 0; o >>= 1) v += __shfl_down_sync(0xffffffffu, v, o);
        int w = tid >> 5;
        if ((tid & 31) == 0) red[w] = v;
        __syncthreads();
        if (tid == 0) {
            float s = red[0] + red[1] + red[2] + red[3];
            atomicAdd(&g_loss, s);
        }
    }

    if (doUpdate) {
        __syncthreads();  // all rs rows written

        // phase 3: S_blk = rs^T @ xs with 8j x 4d register tile per thread
        const int dg = tid & 15;   // d0 = 4*dg
        const int jg = tid >> 4;   // j0 = 8*jg
        float acc[32];
        #pragma unroll
        for (int q = 0; q < 32; q++) acc[q] = 0.0f;

        #pragma unroll 2
        for (int i = 0; i < RPB; i++) {
            float4 xw = *(const float4*)(xs + i * PAD + 4 * dg);
            float4 ra = *(const float4*)(rs + i * PAD + 8 * jg);
            float4 rb = *(const float4*)(rs + i * PAD + 8 * jg + 4);
            float rv[8] = { ra.x, ra.y, ra.z, ra.w, rb.x, rb.y, rb.z, rb.w };
            float xr[4] = { xw.x, xw.y, xw.z, xw.w };
            #pragma unroll
            for (int jj = 0; jj < 8; jj++)
                #pragma unroll
                for (int dd = 0; dd < 4; dd++)
                    acc[jj * 4 + dd] += rv[jj] * xr[dd];
        }
        #pragma unroll
        for (int jj = 0; jj < 8; jj++)
            #pragma unroll
            for (int dd = 0; dd < 4; dd++)
                atomicAdd(&g_S[(8 * jg + jj) * DL + 4 * dg + dd], acc[jj * 4 + dd]);

        // column sums of r
        if (tid < KC) {
            float s = 0.0f;
            #pragma unroll 4
            for (int i = 0; i < RPB; i++) s += rs[i * PAD + tid];
            atomicAdd(&g_rsum[tid], s);
        }
    }
}

// ---------------------------------------------------------------------------
// Centroid update: C = S / (rsum + eps), recompute c2, zero accumulators
// ---------------------------------------------------------------------------
__global__ void update_kernel() {
    int t = threadIdx.x;  // 1024
    float newc[4];
    #pragma unroll
    for (int k = 0; k < 4; k++) {
        int idx = t + k * 1024;
        int j = idx >> 6;
        newc[k] = g_S[idx] / (g_rsum[j] + EPS_C);
    }
    __syncthreads();  // all reads of S/rsum done
    #pragma unroll
    for (int k = 0; k < 4; k++) {
        int idx = t + k * 1024;
        g_C[idx] = newc[k];
        g_S[idx] = 0.0f;
    }
    if (t < KC) g_rsum[t] = 0.0f;
    __syncthreads();  // new C visible block-wide
    if (t < KC) {
        float s = 0.0f;
        #pragma unroll 8
        for (int d = 0; d < DL; d++) { float c = g_C[t * DL + d]; s += c * c; }
        g_c2[t] = s;
    }
}

// ---------------------------------------------------------------------------
// Final combine: out = mean_dec + ALPHA * mean_loss
// ---------------------------------------------------------------------------
__global__ void final_kernel(float* out, int nX, int N) {
    out[0] = g_dec / (float)nX + ALPHA_C * (g_loss / (float)N);
}

// ---------------------------------------------------------------------------
extern "C" void kernel_launch(void* const* d_in, const int* in_sizes, int n_in,
                              void* d_out, int out_size) {
    const float* X   = (const float*)d_in[0];
    const float* enc = (const float*)d_in[1];
    const float* dec = (const float*)d_in[2];
    const int nX = in_sizes[0];
    const int N  = in_sizes[1] / DL;

    const int smemBytes = (KC * DL + KC + 2 * RPB * PAD) * (int)sizeof(float);
    cudaFuncSetAttribute(main_kernel, cudaFuncAttributeMaxDynamicSharedMemorySize, smemBytes);

    init_kernel<<<1, 256>>>(enc);
    decoder_kernel<<<1024, 256>>>((const float4*)X, (const float4*)dec, nX / 4);

    const int blocks = (N + RPB - 1) / RPB;
    for (int it = 0; it < 10; it++) {
        const int last = (it == 9);
        main_kernel<<<blocks, RPB, smemBytes>>>(enc, N, last ? 1 : 0, last ? 0 : 1);
        if (!last) update_kernel<<<1, 1024>>>();
    }
    final_kernel<<<1, 1>>>((float*)d_out, nX, N);
}

// round 4
// speedup vs baseline: 2.5615x; 2.5615x over previous
#include <cuda_runtime.h>
#include <cuda_bf16.h>
#include <cstdint>

// Problem constants: N=65536, D_LAT=64, K=64, D_DATA=512
#define KC      64
#define DL      64
#define RPT     128              // rows per subtile
#define NSUB    2
#define RPB     (RPT * NSUB)     // 256 rows per CTA
#define NTH     128              // 4 warps
#define NIT     10
#define ALPHA_C 0.001f
#define EPS_C   1e-8f
#define POS_INF_F (__int_as_float(0x7f800000))

// smem float offsets
#define XS_STR  76               // 64 data + ones col(64) + pad; 19*4 floats
#define CS_STR  68
#define OFF_XS  0
#define OFF_RS  (OFF_XS + RPT * XS_STR)         // 9728
#define OFF_CS  (OFF_RS + RPT * XS_STR)         // 19456
#define OFF_C2  (OFF_CS + KC * CS_STR)          // 23808
#define OFF_X2  (OFF_C2 + KC)                   // 23872
#define OFF_RED (OFF_X2 + RPT)                  // 24000
#define SMEM_FLOATS (OFF_RED + 32)
#define SMEM_BYTES (SMEM_FLOATS * 4)

// Per-iteration accumulation buffers (iter t writes buf t, iter t+1 reads it)
__device__ float g_S[(NIT - 1) * KC * DL];
__device__ float g_rsum[(NIT - 1) * KC];
__device__ float g_loss;
__device__ float g_dec;

// ---------------------------------------------------------------------------
__device__ __forceinline__ uint32_t tf32r(float x) {
    uint32_t u;
    asm("cvt.rna.tf32.f32 %0, %1;" : "=r"(u) : "f"(x));
    return u;
}

// D (f32) += A (tf32) * B (tf32), m16n8k8
__device__ __forceinline__ void mma_tf32(float* d, const uint32_t* a, uint32_t b0, uint32_t b1) {
    asm volatile(
        "mma.sync.aligned.m16n8k8.row.col.f32.tf32.tf32.f32 "
        "{%0,%1,%2,%3}, {%4,%5,%6,%7}, {%8,%9}, {%0,%1,%2,%3};"
        : "+f"(d[0]), "+f"(d[1]), "+f"(d[2]), "+f"(d[3])
        : "r"(a[0]), "r"(a[1]), "r"(a[2]), "r"(a[3]), "r"(b0), "r"(b1));
}

// ---------------------------------------------------------------------------
__global__ void init_kernel() {
    int t = blockIdx.x * blockDim.x + threadIdx.x;
    int total = (NIT - 1) * KC * DL;
    for (int i = t; i < total; i += gridDim.x * blockDim.x) g_S[i] = 0.0f;
    if (t < (NIT - 1) * KC) g_rsum[t] = 0.0f;
    if (t == 0) { g_loss = 0.0f; g_dec = 0.0f; }
}

// ---------------------------------------------------------------------------
__global__ void decoder_kernel(const float4* __restrict__ X4,
                               const float4* __restrict__ D4, int n4) {
    __shared__ float red[32];
    float acc = 0.0f;
    int stride = gridDim.x * blockDim.x;
    for (int i = blockIdx.x * blockDim.x + threadIdx.x; i < n4; i += stride) {
        float4 x = X4[i], d = D4[i];
        float a = x.x - d.x, b = x.y - d.y, c = x.z - d.z, e = x.w - d.w;
        acc += a * a + b * b;
        acc += c * c + e * e;
    }
    #pragma unroll
    for (int o = 16; o > 0; o >>= 1) acc += __shfl_down_sync(0xffffffffu, acc, o);
    int w = threadIdx.x >> 5;
    if ((threadIdx.x & 31) == 0) red[w] = acc;
    __syncthreads();
    if (threadIdx.x == 0) {
        float s = 0.0f;
        int nw = blockDim.x >> 5;
        for (int i = 0; i < nw; i++) s += red[i];
        atomicAdd(&g_dec, s);
    }
}

// ---------------------------------------------------------------------------
// Main fused iteration kernel (mma.sync tf32)
// ---------------------------------------------------------------------------
extern __shared__ float sf[];

__global__ __launch_bounds__(NTH, 2)
void main_kernel(const float* __restrict__ enc, int N, int it) {
    uint32_t* su = (uint32_t*)sf;
    float* xs  = sf + OFF_XS;   uint32_t* xsu = su + OFF_XS;
    float* rsm = sf + OFF_RS;   uint32_t* rsu = su + OFF_RS;
    float* Cs  = sf + OFF_CS;   uint32_t* Csu = su + OFF_CS;
    float* c2s = sf + OFF_C2;
    float* x2s = sf + OFF_X2;
    float* red = sf + OFF_RED;

    const int tid  = threadIdx.x;
    const int wid  = tid >> 5;
    const int lane = tid & 31;
    const int g    = lane >> 2;     // groupID
    const int tg   = lane & 3;      // threadID_in_group
    const bool last = (it == NIT - 1);
    const int row_base = blockIdx.x * RPB;

    // --- C setup: C[j][d] from prev-iter S/rsum (or enc rows for it=0) ---
    {
        const int j = tid >> 1, h = tid & 1;   // 32 cols per thread
        float part = 0.0f;
        float invd = 0.0f;
        if (it > 0) invd = 1.0f / (g_rsum[(it - 1) * KC + j] + EPS_C);
        const float* src = (it == 0) ? (enc + j * DL) : (g_S + (it - 1) * KC * DL + j * DL);
        #pragma unroll 8
        for (int c = 0; c < 32; c++) {
            int d = h * 32 + c;
            float v = src[d];
            if (it > 0) v *= invd;
            uint32_t u = tf32r(v);
            float vr = __uint_as_float(u);
            part += vr * vr;
            Csu[j * CS_STR + d] = u;
        }
        part += __shfl_xor_sync(0xffffffffu, part, 1);
        if (h == 0) c2s[j] = part;
    }

    // GEMM2 accumulators: warp handles clusters j = 16*wid + g (+8), cols 8n+2tg(+1)
    float sfr[9][4];
    #pragma unroll
    for (int n = 0; n < 9; n++)
        #pragma unroll
        for (int q = 0; q < 4; q++) sfr[n][q] = 0.0f;

    float lossacc = 0.0f;

    for (int s = 0; s < NSUB; s++) {
        const int row0 = row_base + s * RPT;
        __syncthreads();   // Cs ready (s=0); xs/rs free from prev subtile (s>0)

        // --- load x row (thread tid -> local row tid), tf32 round, x2 ---
        {
            const float4* rowp = (const float4*)(enc + (size_t)(row0 + tid) * DL);
            float x2 = 0.0f;
            #pragma unroll
            for (int q = 0; q < 16; q++) {
                float4 v = rowp[q];
                uint32_t u0 = tf32r(v.x), u1 = tf32r(v.y), u2 = tf32r(v.z), u3 = tf32r(v.w);
                float f0 = __uint_as_float(u0), f1 = __uint_as_float(u1);
                float f2 = __uint_as_float(u2), f3 = __uint_as_float(u3);
                x2 += f0 * f0 + f1 * f1;
                x2 += f2 * f2 + f3 * f3;
                uint4 pk; pk.x = u0; pk.y = u1; pk.z = u2; pk.w = u3;
                *(uint4*)(xsu + tid * XS_STR + 4 * q) = pk;
            }
            x2s[tid] = x2;
            xs[tid * XS_STR + 64] = 1.0f;      // ones column -> rsum via GEMM2
            #pragma unroll
            for (int c = 65; c < XS_STR; c++) xs[tid * XS_STR + c] = 0.0f;
        }
        __syncthreads();

        // --- GEMM1: D[32x64] = x[32x64] @ C^T, k-outer ---
        const int wr0 = wid * 32;   // warp's local row base
        float dfr[2][8][4];
        #pragma unroll
        for (int m = 0; m < 2; m++)
            #pragma unroll
            for (int n = 0; n < 8; n++)
                #pragma unroll
                for (int q = 0; q < 4; q++) dfr[m][n][q] = 0.0f;

        #pragma unroll
        for (int k = 0; k < 8; k++) {
            uint32_t afr[2][4];
            #pragma unroll
            for (int m = 0; m < 2; m++) {
                int rb = wr0 + 16 * m;
                afr[m][0] = xsu[(rb + g) * XS_STR + 8 * k + tg];
                afr[m][1] = xsu[(rb + g + 8) * XS_STR + 8 * k + tg];
                afr[m][2] = xsu[(rb + g) * XS_STR + 8 * k + tg + 4];
                afr[m][3] = xsu[(rb + g + 8) * XS_STR + 8 * k + tg + 4];
            }
            #pragma unroll
            for (int n = 0; n < 8; n++) {
                uint32_t b0 = Csu[(8 * n + g) * CS_STR + 8 * k + tg];
                uint32_t b1 = Csu[(8 * n + g) * CS_STR + 8 * k + tg + 4];
                mma_tf32(dfr[0][n], afr[0], b0, b1);
                mma_tf32(dfr[1][n], afr[1], b0, b1);
            }
        }

        // --- epilogue: d2, softmax, write r (or loss) ---
        float c2v[16];
        #pragma unroll
        for (int n = 0; n < 8; n++) {
            c2v[2 * n]     = c2s[8 * n + 2 * tg];
            c2v[2 * n + 1] = c2s[8 * n + 2 * tg + 1];
        }
        #pragma unroll
        for (int m = 0; m < 2; m++) {
            #pragma unroll
            for (int h = 0; h < 2; h++) {
                const int lr = wr0 + 16 * m + 8 * h + g;   // local row
                const float x2v = x2s[lr];
                float d2v[16];
                float mn = POS_INF_F;
                #pragma unroll
                for (int n = 0; n < 8; n++) {
                    float v0 = fmaxf(x2v + c2v[2 * n]     - 2.0f * dfr[m][n][2 * h],     0.0f);
                    float v1 = fmaxf(x2v + c2v[2 * n + 1] - 2.0f * dfr[m][n][2 * h + 1], 0.0f);
                    d2v[2 * n] = v0; d2v[2 * n + 1] = v1;
                    mn = fminf(mn, fminf(v0, v1));
                }
                mn = fminf(mn, __shfl_xor_sync(0xffffffffu, mn, 1));
                mn = fminf(mn, __shfl_xor_sync(0xffffffffu, mn, 2));
                float Z = 0.0f, ed2 = 0.0f;
                float ev[16];
                #pragma unroll
                for (int q = 0; q < 16; q++) {
                    float e = __expf(mn - d2v[q]);
                    Z += e; ed2 += e * d2v[q];
                    ev[q] = e;
                }
                Z   += __shfl_xor_sync(0xffffffffu, Z, 1);
                Z   += __shfl_xor_sync(0xffffffffu, Z, 2);
                const float inv = 1.0f / Z;
                if (last) {
                    ed2 += __shfl_xor_sync(0xffffffffu, ed2, 1);
                    ed2 += __shfl_xor_sync(0xffffffffu, ed2, 2);
                    lossacc += 0.25f * ed2 * inv;   // quad holds 4 copies
                } else {
                    #pragma unroll
                    for (int n = 0; n < 8; n++) {
                        rsu[lr * XS_STR + 8 * n + 2 * tg]     = tf32r(ev[2 * n] * inv);
                        rsu[lr * XS_STR + 8 * n + 2 * tg + 1] = tf32r(ev[2 * n + 1] * inv);
                    }
                }
            }
        }

        if (!last) {
            __syncthreads();   // rs complete
            // --- GEMM2: S[64x72] += r^T[64x128] @ xext[128x72] ---
            const int j0 = 16 * wid;
            #pragma unroll
            for (int kk = 0; kk < 16; kk++) {
                uint32_t afr[4];
                afr[0] = rsu[(8 * kk + tg) * XS_STR + j0 + g];
                afr[1] = rsu[(8 * kk + tg) * XS_STR + j0 + g + 8];
                afr[2] = rsu[(8 * kk + tg + 4) * XS_STR + j0 + g];
                afr[3] = rsu[(8 * kk + tg + 4) * XS_STR + j0 + g + 8];
                #pragma unroll
                for (int n = 0; n < 9; n++) {
                    uint32_t b0 = xsu[(8 * kk + tg) * XS_STR + 8 * n + g];
                    uint32_t b1 = xsu[(8 * kk + tg + 4) * XS_STR + 8 * n + g];
                    mma_tf32(sfr[n], afr, b0, b1);
                }
            }
        }
    }

    if (!last) {
        // GEMM2 epilogue: atomics to g_S / g_rsum
        float* gs = g_S + it * KC * DL;
        const int j0 = 16 * wid;
        #pragma unroll
        for (int h = 0; h < 2; h++) {
            const int j = j0 + g + 8 * h;
            #pragma unroll
            for (int n = 0; n < 8; n++) {
                atomicAdd(&gs[j * DL + 8 * n + 2 * tg],     sfr[n][2 * h]);
                atomicAdd(&gs[j * DL + 8 * n + 2 * tg + 1], sfr[n][2 * h + 1]);
            }
            if (tg == 0)   // col 64 of extended B = rsum
                atomicAdd(&g_rsum[it * KC + j], sfr[8][2 * h]);
        }
    } else {
        float v = lossacc;
        #pragma unroll
        for (int o = 16; o > 0; o >>= 1) v += __shfl_down_sync(0xffffffffu, v, o);
        if (lane == 0) red[wid] = v;
        __syncthreads();
        if (tid == 0) atomicAdd(&g_loss, red[0] + red[1] + red[2] + red[3]);
    }
}

// ---------------------------------------------------------------------------
__global__ void final_kernel(float* out, int nX, int N) {
    out[0] = g_dec / (float)nX + ALPHA_C * (g_loss / (float)N);
}

// ---------------------------------------------------------------------------
extern "C" void kernel_launch(void* const* d_in, const int* in_sizes, int n_in,
                              void* d_out, int out_size) {
    const float* X   = (const float*)d_in[0];
    const float* enc = (const float*)d_in[1];
    const float* dec = (const float*)d_in[2];
    const int nX = in_sizes[0];
    const int N  = in_sizes[1] / DL;

    cudaFuncSetAttribute(main_kernel, cudaFuncAttributeMaxDynamicSharedMemorySize, SMEM_BYTES);

    init_kernel<<<40, 1024>>>();
    decoder_kernel<<<1024, 256>>>((const float4*)X, (const float4*)dec, nX / 4);

    const int blocks = N / RPB;
    for (int it = 0; it < NIT; it++) {
        main_kernel<<<blocks, NTH, SMEM_BYTES>>>(enc, N, it);
    }
    final_kernel<<<1, 1>>>((float*)d_out, nX, N);
}

// round 5
// speedup vs baseline: 2.6026x; 1.0160x over previous
#include <cuda_runtime.h>
#include <cuda_bf16.h>
#include <cstdint>

// Problem constants: N=65536, D_LAT=64, K=64, D_DATA=512
#define KC      64
#define DL      64
#define RPT     128              // rows per subtile
#define NSUB    2
#define RPB     (RPT * NSUB)     // 256 rows per CTA
#define NTH     256              // 8 warps
#define NIT     10
#define ALPHA_C 0.001f
#define EPS_C   1e-8f
#define POS_INF_F (__int_as_float(0x7f800000))

// smem float offsets
#define XS_STR  76               // 64 data + ones col(64) + zero pad 65..71
#define CS_STR  68
#define OFF_XS  0
#define OFF_RS  (OFF_XS + RPT * XS_STR)         // 9728
#define OFF_CS  (OFF_RS + RPT * XS_STR)         // 19456
#define OFF_C2  (OFF_CS + KC * CS_STR)          // 23808
#define OFF_X2  (OFF_C2 + KC)                   // 23872
#define OFF_RED (OFF_X2 + RPT)                  // 24000
#define SMEM_FLOATS (OFF_RED + 32)
#define SMEM_BYTES (SMEM_FLOATS * 4)

// Per-iteration accumulation buffers (iter t writes buf t, iter t+1 reads it)
__device__ float g_S[(NIT - 1) * KC * DL];
__device__ float g_rsum[(NIT - 1) * KC];
__device__ float g_loss;
__device__ float g_dec;

// ---------------------------------------------------------------------------
__device__ __forceinline__ uint32_t tf32r(float x) {
    uint32_t u;
    asm("cvt.rna.tf32.f32 %0, %1;" : "=r"(u) : "f"(x));
    return u;
}

// D (f32) += A (tf32) * B (tf32), m16n8k8
__device__ __forceinline__ void mma_tf32(float* d, const uint32_t* a, uint32_t b0, uint32_t b1) {
    asm volatile(
        "mma.sync.aligned.m16n8k8.row.col.f32.tf32.tf32.f32 "
        "{%0,%1,%2,%3}, {%4,%5,%6,%7}, {%8,%9}, {%0,%1,%2,%3};"
        : "+f"(d[0]), "+f"(d[1]), "+f"(d[2]), "+f"(d[3])
        : "r"(a[0]), "r"(a[1]), "r"(a[2]), "r"(a[3]), "r"(b0), "r"(b1));
}

// ---------------------------------------------------------------------------
__global__ void init_kernel() {
    int t = blockIdx.x * blockDim.x + threadIdx.x;
    int total = (NIT - 1) * KC * DL;
    for (int i = t; i < total; i += gridDim.x * blockDim.x) g_S[i] = 0.0f;
    if (t < (NIT - 1) * KC) g_rsum[t] = 0.0f;
    if (t == 0) { g_loss = 0.0f; g_dec = 0.0f; }
}

// ---------------------------------------------------------------------------
// Main fused iteration kernel (mma.sync tf32) + decoder-loss chunk
// ---------------------------------------------------------------------------
extern __shared__ float sf[];

__global__ __launch_bounds__(NTH, 2)
void main_kernel(const float* __restrict__ enc,
                 const float4* __restrict__ X4, const float4* __restrict__ D4,
                 int d_start, int d_end, int N, int it) {
    uint32_t* su = (uint32_t*)sf;
    float* xs  = sf + OFF_XS;   uint32_t* xsu = su + OFF_XS;
    uint32_t* rsu = su + OFF_RS;
    uint32_t* Csu = su + OFF_CS;
    float* c2s = sf + OFF_C2;
    float* x2s = sf + OFF_X2;
    float* red = sf + OFF_RED;

    const int tid  = threadIdx.x;
    const int wid  = tid >> 5;
    const int lane = tid & 31;
    const int g    = lane >> 2;     // groupID
    const int tg   = lane & 3;      // threadID_in_group
    const bool last = (it == NIT - 1);
    const int row_base = blockIdx.x * RPB;

    // --- C setup: C[j][d] from prev-iter S/rsum (or enc rows for it=0) ---
    {
        const int j = tid >> 2, h = tid & 3;   // 16 cols per thread
        float part = 0.0f;
        float invd = 0.0f;
        if (it > 0) invd = 1.0f / (g_rsum[(it - 1) * KC + j] + EPS_C);
        const float* src = (it == 0) ? (enc + j * DL) : (g_S + (it - 1) * KC * DL + j * DL);
        #pragma unroll
        for (int c = 0; c < 16; c++) {
            int d = h * 16 + c;
            float v = src[d];
            if (it > 0) v *= invd;
            uint32_t u = tf32r(v);
            float vr = __uint_as_float(u);
            part += vr * vr;
            Csu[j * CS_STR + d] = u;
        }
        part += __shfl_xor_sync(0xffffffffu, part, 1);
        part += __shfl_xor_sync(0xffffffffu, part, 2);
        if (h == 0) c2s[j] = part;
    }

    // GEMM2 accumulators: warp (mg = wid&3, nh = wid>>2)
    //   rows j = 16*mg + g (+8), n-tiles: nh==0 -> n 0..3, nh==1 -> n 4..8
    const int mg = wid & 3, nh = wid >> 2;
    const int nbase = nh * 4, ntiles = nh ? 5 : 4;
    float sfr[5][4];
    #pragma unroll
    for (int n = 0; n < 5; n++)
        #pragma unroll
        for (int q = 0; q < 4; q++) sfr[n][q] = 0.0f;

    float lossacc = 0.0f;

    for (int s = 0; s < NSUB; s++) {
        const int row0 = row_base + s * RPT;
        __syncthreads();   // Cs ready (s=0); xs/rs free from prev subtile (s>0)

        // --- load x rows (2 threads per row), tf32 round, x2 ---
        {
            const int row = tid >> 1, half = tid & 1;
            const float4* rowp = (const float4*)(enc + (size_t)(row0 + row) * DL) + 8 * half;
            float x2 = 0.0f;
            #pragma unroll
            for (int q = 0; q < 8; q++) {
                float4 v = rowp[q];
                uint32_t u0 = tf32r(v.x), u1 = tf32r(v.y), u2 = tf32r(v.z), u3 = tf32r(v.w);
                float f0 = __uint_as_float(u0), f1 = __uint_as_float(u1);
                float f2 = __uint_as_float(u2), f3 = __uint_as_float(u3);
                x2 += f0 * f0 + f1 * f1;
                x2 += f2 * f2 + f3 * f3;
                uint4 pk; pk.x = u0; pk.y = u1; pk.z = u2; pk.w = u3;
                *(uint4*)(xsu + row * XS_STR + 32 * half + 4 * q) = pk;
            }
            x2 += __shfl_xor_sync(0xffffffffu, x2, 1);
            if (half == 0) {
                x2s[row] = x2;
            } else {
                xs[row * XS_STR + 64] = 1.0f;      // ones column -> rsum via GEMM2
                #pragma unroll
                for (int c = 65; c < 72; c++) xs[row * XS_STR + c] = 0.0f;
            }
        }
        __syncthreads();

        // --- GEMM1: warp's D[16x64] = x[16x64] @ C^T, k-outer ---
        const int wr0 = wid * 16;   // warp's local row base
        float dfr[8][4];
        #pragma unroll
        for (int n = 0; n < 8; n++)
            #pragma unroll
            for (int q = 0; q < 4; q++) dfr[n][q] = 0.0f;

        #pragma unroll
        for (int k = 0; k < 8; k++) {
            uint32_t afr[4];
            afr[0] = xsu[(wr0 + g) * XS_STR + 8 * k + tg];
            afr[1] = xsu[(wr0 + g + 8) * XS_STR + 8 * k + tg];
            afr[2] = xsu[(wr0 + g) * XS_STR + 8 * k + tg + 4];
            afr[3] = xsu[(wr0 + g + 8) * XS_STR + 8 * k + tg + 4];
            #pragma unroll
            for (int n = 0; n < 8; n++) {
                uint32_t b0 = Csu[(8 * n + g) * CS_STR + 8 * k + tg];
                uint32_t b1 = Csu[(8 * n + g) * CS_STR + 8 * k + tg + 4];
                mma_tf32(dfr[n], afr, b0, b1);
            }
        }

        // --- epilogue: d2, softmax, write r (or loss) ---
        float c2v[16];
        #pragma unroll
        for (int n = 0; n < 8; n++) {
            c2v[2 * n]     = c2s[8 * n + 2 * tg];
            c2v[2 * n + 1] = c2s[8 * n + 2 * tg + 1];
        }
        #pragma unroll
        for (int h = 0; h < 2; h++) {
            const int lr = wr0 + 8 * h + g;   // local row
            const float x2v = x2s[lr];
            float d2v[16];
            float mn = POS_INF_F;
            #pragma unroll
            for (int n = 0; n < 8; n++) {
                float v0 = fmaxf(x2v + c2v[2 * n]     - 2.0f * dfr[n][2 * h],     0.0f);
                float v1 = fmaxf(x2v + c2v[2 * n + 1] - 2.0f * dfr[n][2 * h + 1], 0.0f);
                d2v[2 * n] = v0; d2v[2 * n + 1] = v1;
                mn = fminf(mn, fminf(v0, v1));
            }
            mn = fminf(mn, __shfl_xor_sync(0xffffffffu, mn, 1));
            mn = fminf(mn, __shfl_xor_sync(0xffffffffu, mn, 2));
            float Z = 0.0f, ed2 = 0.0f;
            float ev[16];
            #pragma unroll
            for (int q = 0; q < 16; q++) {
                float e = __expf(mn - d2v[q]);
                Z += e; ed2 += e * d2v[q];
                ev[q] = e;
            }
            Z += __shfl_xor_sync(0xffffffffu, Z, 1);
            Z += __shfl_xor_sync(0xffffffffu, Z, 2);
            const float inv = 1.0f / Z;
            if (last) {
                ed2 += __shfl_xor_sync(0xffffffffu, ed2, 1);
                ed2 += __shfl_xor_sync(0xffffffffu, ed2, 2);
                lossacc += 0.25f * ed2 * inv;   // quad holds 4 copies
            } else {
                #pragma unroll
                for (int n = 0; n < 8; n++) {
                    rsu[lr * XS_STR + 8 * n + 2 * tg]     = tf32r(ev[2 * n] * inv);
                    rsu[lr * XS_STR + 8 * n + 2 * tg + 1] = tf32r(ev[2 * n + 1] * inv);
                }
            }
        }

        if (!last) {
            __syncthreads();   // rs complete
            // --- GEMM2: S[64x72] += r^T[64x128] @ xext[128x72] (n-split by nh) ---
            const int j0 = 16 * mg;
            #pragma unroll
            for (int kk = 0; kk < 16; kk++) {
                uint32_t afr[4];
                afr[0] = rsu[(8 * kk + tg) * XS_STR + j0 + g];
                afr[1] = rsu[(8 * kk + tg) * XS_STR + j0 + g + 8];
                afr[2] = rsu[(8 * kk + tg + 4) * XS_STR + j0 + g];
                afr[3] = rsu[(8 * kk + tg + 4) * XS_STR + j0 + g + 8];
                #pragma unroll
                for (int n = 0; n < 5; n++) {
                    if (n < ntiles) {
                        uint32_t b0 = xsu[(8 * kk + tg) * XS_STR + 8 * (nbase + n) + g];
                        uint32_t b1 = xsu[(8 * kk + tg + 4) * XS_STR + 8 * (nbase + n) + g];
                        mma_tf32(sfr[n], afr, b0, b1);
                    }
                }
            }
        }
    }

    if (!last) {
        // GEMM2 epilogue: atomics to g_S / g_rsum
        float* gs = g_S + it * KC * DL;
        const int j0 = 16 * mg;
        #pragma unroll
        for (int h = 0; h < 2; h++) {
            const int j = j0 + g + 8 * h;
            #pragma unroll
            for (int n = 0; n < 5; n++) {
                const int nn = nbase + n;
                if (n < ntiles && nn < 8) {
                    atomicAdd(&gs[j * DL + 8 * nn + 2 * tg],     sfr[n][2 * h]);
                    atomicAdd(&gs[j * DL + 8 * nn + 2 * tg + 1], sfr[n][2 * h + 1]);
                }
            }
            if (nh == 1 && tg == 0)   // n==8: ones column = rsum
                atomicAdd(&g_rsum[it * KC + j], sfr[4][2 * h]);
        }
    } else {
        float v = lossacc;
        #pragma unroll
        for (int o = 16; o > 0; o >>= 1) v += __shfl_down_sync(0xffffffffu, v, o);
        __syncthreads();
        if (lane == 0) red[wid] = v;
        __syncthreads();
        if (tid == 0) {
            float sum = 0.0f;
            #pragma unroll
            for (int w = 0; w < 8; w++) sum += red[w];
            atomicAdd(&g_loss, sum);
        }
    }

    // --- fused decoder-loss chunk (this iteration's 1/NIT of X/decoding) ---
    {
        float acc = 0.0f;
        const int stride = gridDim.x * NTH;
        for (int i = d_start + blockIdx.x * NTH + tid; i < d_end; i += stride) {
            float4 x = X4[i], d = D4[i];
            float a = x.x - d.x, b = x.y - d.y, c = x.z - d.z, e = x.w - d.w;
            acc += a * a + b * b;
            acc += c * c + e * e;
        }
        #pragma unroll
        for (int o = 16; o > 0; o >>= 1) acc += __shfl_down_sync(0xffffffffu, acc, o);
        __syncthreads();
        if (lane == 0) red[wid] = acc;
        __syncthreads();
        if (tid == 0) {
            float sum = 0.0f;
            #pragma unroll
            for (int w = 0; w < 8; w++) sum += red[w];
            atomicAdd(&g_dec, sum);
        }
    }
}

// ---------------------------------------------------------------------------
__global__ void final_kernel(float* out, int nX, int N) {
    out[0] = g_dec / (float)nX + ALPHA_C * (g_loss / (float)N);
}

// ---------------------------------------------------------------------------
extern "C" void kernel_launch(void* const* d_in, const int* in_sizes, int n_in,
                              void* d_out, int out_size) {
    const float* X   = (const float*)d_in[0];
    const float* enc = (const float*)d_in[1];
    const float* dec = (const float*)d_in[2];
    const int nX = in_sizes[0];
    const int N  = in_sizes[1] / DL;
    const int n4 = nX / 4;

    cudaFuncSetAttribute(main_kernel, cudaFuncAttributeMaxDynamicSharedMemorySize, SMEM_BYTES);

    init_kernel<<<40, 1024>>>();

    const int blocks = N / RPB;
    const int chunk = (n4 + NIT - 1) / NIT;
    for (int it = 0; it < NIT; it++) {
        int ds = it * chunk;
        int de = (it == NIT - 1) ? n4 : ds + chunk;
        main_kernel<<<blocks, NTH, SMEM_BYTES>>>(
            enc, (const float4*)X, (const float4*)dec, ds, de, N, it);
    }
    final_kernel<<<1, 1>>>((float*)d_out, nX, N);
}